// round 7
// baseline (speedup 1.0000x reference)
#include <cuda_runtime.h>
#include <cuda_fp16.h>
#include <cstdint>
#include <cstring>

#define Bv 4
#define Nv 256
#define Dv 256
#define Mv (Bv*Nv*Nv)     // 262144 pair rows
#define BIv (Bv*Nv)       // 1024 (b,i) rows

// scratch (no allocations allowed)
__device__ __align__(16) float g_s12[BIv * 512];     // s1 (cols 0..255), s2+b_in (cols 256..511)
__device__ __align__(16) float g_resid[BIv * Dv];
__device__ __align__(16) float g_part[4096 * 256];   // per-CTA weighted column partials
__device__ __align__(16) float g_zpart[4096];        // per-CTA exp-sum partials
// W_in[512:768,:] fp16, layout [c32][kg16][n][16perm]
__device__ __align__(16) __half g_w3h[256 * 256];

__device__ __forceinline__ uint32_t smem_u32(const void* p) {
    uint32_t a;
    asm("{ .reg .u64 t; cvta.to.shared.u64 t, %1; cvt.u32.u64 %0, t; }" : "=r"(a) : "l"(p));
    return a;
}
__device__ __forceinline__ uint32_t f2h2(float a, float b) {
    __half2 h = __floats2half2_rn(a, b);
    uint32_t u; memcpy(&u, &h, 4); return u;
}
__device__ __forceinline__ void mma_f16(float* d, const uint32_t* a, const uint32_t* b) {
    asm volatile(
        "mma.sync.aligned.m16n8k16.row.col.f32.f16.f16.f32 "
        "{%0,%1,%2,%3}, {%4,%5,%6,%7}, {%8,%9}, {%0,%1,%2,%3};"
        : "+f"(d[0]), "+f"(d[1]), "+f"(d[2]), "+f"(d[3])
        : "r"(a[0]), "r"(a[1]), "r"(a[2]), "r"(a[3]), "r"(b[0]), "r"(b[1]));
}
__device__ __forceinline__ void ldsm4(uint32_t* r, uint32_t addr) {
    asm volatile("ldmatrix.sync.aligned.m8n8.x4.shared.b16 {%0,%1,%2,%3}, [%4];"
        : "=r"(r[0]), "=r"(r[1]), "=r"(r[2]), "=r"(r[3]) : "r"(addr));
}
#define CP_ASYNC16(s, g) \
    asm volatile("cp.async.ca.shared.global [%0], [%1], 16;" :: "r"(s), "l"(g))
#define CP_COMMIT()  asm volatile("cp.async.commit_group;" ::: "memory")
#define CP_WAIT1()   asm volatile("cp.async.wait_group 1;" ::: "memory")

// ===========================================================================
// k_prep: fp16 permuted copy of W_in[512:768,:]
__global__ void k_prep(const float* __restrict__ Win) {
    int k = blockIdx.x, n = threadIdx.x;
    int c = k >> 5, kg = (k >> 4) & 1, kk = k & 15;
    int t = (kk & 7) >> 1;
    int u = (kk & 1) + ((kk >> 3) << 1);
    int p = t * 4 + u;
    g_w3h[(((size_t)(c * 2 + kg)) * 256 + n) * 16 + p] =
        __float2half_rn(Win[(size_t)(512 + k) * 256 + n]);
}

// ===========================================================================
// s12: [1024,256] (nodes) @ W_in[0:512,:] -> g_s12 [1024,512] (fp32 exact)
__global__ void k_s12(const float* __restrict__ nodes, const float* __restrict__ Win,
                      const float* __restrict__ b_in) {
    __shared__ float As[16][64];
    __shared__ float Bs[16][64];
    int tid = threadIdx.x;
    int tx = tid & 15, ty = tid >> 4;
    int row0 = blockIdx.x * 64;
    int n0   = blockIdx.y * 64;
    float c[4][4] = {};
    for (int k0 = 0; k0 < 256; k0 += 16) {
        {
            int r = tid >> 2, kq = tid & 3;
            float4 v = *(const float4*)&nodes[(size_t)(row0 + r) * 256 + k0 + kq * 4];
            As[kq*4+0][r] = v.x; As[kq*4+1][r] = v.y; As[kq*4+2][r] = v.z; As[kq*4+3][r] = v.w;
        }
        {
            int k = tid >> 4, nq = tid & 15;
            int n = n0 + nq * 4;
            const float* src = (n < 256) ? &Win[(size_t)(k0 + k) * 256 + n]
                                         : &Win[(size_t)(256 + k0 + k) * 256 + (n - 256)];
            *(float4*)&Bs[k][nq*4] = *(const float4*)src;
        }
        __syncthreads();
#pragma unroll
        for (int k = 0; k < 16; k++) {
            float a[4], b[4];
            *(float4*)a = *(float4*)&As[k][ty*4];
            *(float4*)b = *(float4*)&Bs[k][tx*4];
#pragma unroll
            for (int i = 0; i < 4; i++)
#pragma unroll
                for (int j = 0; j < 4; j++) c[i][j] += a[i] * b[j];
        }
        __syncthreads();
    }
#pragma unroll
    for (int i = 0; i < 4; i++) {
        int row = row0 + ty*4 + i;
#pragma unroll
        for (int j = 0; j < 4; j++) {
            int n = n0 + tx*4 + j;
            float v = c[i][j] + (n >= 256 ? b_in[n - 256] : 0.f);
            g_s12[(size_t)row * 512 + n] = v;
        }
    }
}

// ===========================================================================
// k_main: fp16 mma m16n8k16, BM=64 x BN=256 x BK=32, 256 thr.
// Epilogue: cat store + coef + UNNORMALIZED softmax partials (w = exp(logit)),
// partial weighted column sums into g_part / g_zpart.
#define A_STG_B 5120                     // 64 rows x 80B
#define B_STG_B 16384                    // 32k x 256n x 2B
#define OFF_A    0                       // 2 stages: 10240
#define OFF_B    10240                   // 3 stages: 49152 (reused as part[] post-loop)
#define OFF_S1   59392
#define OFF_WC   60416
#define OFF_RED  61440                   // 64*4 floats = 1024B
#define OFF_WROW 62464                   // 64 floats
#define SMEM_MAIN_BYTES 62720

__global__ void __launch_bounds__(256, 2) k_main(const float* __restrict__ edges,
                                                 const float* __restrict__ Wcoef,
                                                 const float* __restrict__ aux,
                                                 const float* __restrict__ bcoef,
                                                 float* __restrict__ cat) {
    extern __shared__ __align__(128) char smc[];
    float* s1s  = (float*)(smc + OFF_S1);
    float* wcs  = (float*)(smc + OFF_WC);
    float* red  = (float*)(smc + OFF_RED);
    float* wrow = (float*)(smc + OFF_WROW);

    int tid = threadIdx.x;
    int lane = tid & 31, wid = tid >> 5;
    int gid = lane >> 2, tig = lane & 3;
    int wm = wid & 1, wn = wid >> 1;
    int m0w = wm * 32, n0w = wn * 64;

    int row0 = blockIdx.x * 64;
    int bi = row0 >> 8;
    int b  = bi >> 8;

    s1s[tid] = g_s12[(size_t)bi * 512 + tid];
    wcs[tid] = Wcoef[tid];

    int ar = tid >> 2, aj = tid & 3;
    const float* a_src = &edges[(size_t)(row0 + ar) * 256 + aj * 8];
    uint32_t a_sts = smem_u32(smc + OFF_A) + (uint32_t)(ar * 80 + aj * 16);

    uint32_t b_smem = smem_u32(smc + OFF_B);
    const char* b_gbase = (const char*)g_w3h;

    float4 rb[2][2];
    int lrow = ((lane >> 3) & 1) * 8 + (lane & 7);
    int lkb  = (lane >> 4) * 16;

#define LDGA(c, bf) do { \
        rb[bf][0] = *(const float4*)(a_src + (c) * 32); \
        rb[bf][1] = *(const float4*)(a_src + (c) * 32 + 4); } while (0)
#define STSA(c, bf) do { \
        uint4 t_; \
        t_.x = f2h2(rb[bf][0].x, rb[bf][0].y); \
        t_.y = f2h2(rb[bf][0].z, rb[bf][0].w); \
        t_.z = f2h2(rb[bf][1].x, rb[bf][1].y); \
        t_.w = f2h2(rb[bf][1].z, rb[bf][1].w); \
        asm volatile("st.shared.v4.b32 [%0], {%1,%2,%3,%4};" \
            :: "r"(a_sts + ((c) & 1) * A_STG_B), "r"(t_.x), "r"(t_.y), "r"(t_.z), "r"(t_.w) \
            : "memory"); } while (0)
#define CPB(c) do { \
        int s3_ = (c) - ((c) / 3) * 3; \
        _Pragma("unroll") \
        for (int i_ = 0; i_ < 4; i_++) { \
            int u_ = tid + i_ * 256; \
            int kg_ = u_ >> 9, n_ = (u_ >> 1) & 255, h_ = u_ & 1; \
            uint32_t d_ = b_smem + s3_ * B_STG_B + kg_ * 8192 + n_ * 32 + h_ * 16; \
            const void* s_ = b_gbase + (((size_t)((c) * 2 + kg_)) * 256 + n_) * 32 + h_ * 16; \
            CP_ASYNC16(d_, s_); \
        } } while (0)

    // ---- prologue
    LDGA(0, 0); LDGA(1, 1);
    CPB(0); CP_COMMIT();
    CPB(1); CP_COMMIT();
    STSA(0, 0);
    CP_WAIT1();
    __syncthreads();

    float acc[2][8][4] = {};

#pragma unroll
    for (int c = 0; c < 8; c++) {
        if (c + 2 < 8) CPB(c + 2);
        CP_COMMIT();
        if (c + 1 < 8) STSA(c + 1, (c + 1) & 1);
        if (c + 2 < 8) LDGA(c + 2, c & 1);

        uint32_t aBase = smem_u32(smc + OFF_A) + (c & 1) * A_STG_B;
        const char* Bs_ = smc + OFF_B + (c - (c / 3) * 3) * B_STG_B;
#pragma unroll
        for (int ks = 0; ks < 2; ks++) {
            uint32_t a[2][4];
#pragma unroll
            for (int mf = 0; mf < 2; mf++)
                ldsm4(a[mf], aBase + (uint32_t)((m0w + mf * 16 + lrow) * 80 + ks * 32 + lkb));
            uint32_t bf[8][2];
#pragma unroll
            for (int nf = 0; nf < 8; nf++) {
                int n = n0w + nf * 8 + gid;
                uint2 pv = *(const uint2*)(Bs_ + ks * 8192 + n * 32 + tig * 8);
                bf[nf][0] = pv.x; bf[nf][1] = pv.y;
            }
#pragma unroll
            for (int mf = 0; mf < 2; mf++)
#pragma unroll
                for (int nf = 0; nf < 8; nf++)
                    mma_f16(acc[mf][nf], a[mf], bf[nf]);
        }
        CP_WAIT1();
        __syncthreads();
    }

    // ---- epilogue 1: cat store + coef partials; keep relu'd values in acc
#pragma unroll
    for (int mf = 0; mf < 2; mf++) {
#pragma unroll
        for (int rr = 0; rr < 2; rr++) {
            int row_local = m0w + mf * 16 + gid + rr * 8;
            int m  = row0 + row_local;
            int jj = (row0 & 255) + row_local;
            const float* s2p = &g_s12[((size_t)(b * 256 + jj)) * 512 + 256];
            float* catp = &cat[(size_t)m * 256];
            float csum = 0.f;
#pragma unroll
            for (int nf = 0; nf < 8; nf++) {
                int nl = n0w + nf * 8 + tig * 2;
                float v0 = acc[mf][nf][rr*2]   + s1s[nl]   + s2p[nl];
                float v1 = acc[mf][nf][rr*2+1] + s1s[nl+1] + s2p[nl+1];
                v0 = fmaxf(v0, 0.f); v1 = fmaxf(v1, 0.f);
                acc[mf][nf][rr*2]   = v0;       // keep for weighted sum
                acc[mf][nf][rr*2+1] = v1;
                csum += v0 * wcs[nl] + v1 * wcs[nl + 1];
                float2 st = { v0, v1 };
                *(float2*)&catp[nl] = st;
            }
            csum += __shfl_xor_sync(0xffffffffu, csum, 1);
            csum += __shfl_xor_sync(0xffffffffu, csum, 2);
            if (tig == 0) red[row_local * 4 + wn] = csum;
        }
    }
    __syncthreads();

    // ---- epilogue 2: w_j = exp(aux + coef + bc); Z partial
    if (tid < 64) {
        float coef = red[tid*4] + red[tid*4+1] + red[tid*4+2] + red[tid*4+3];
        wrow[tid] = __expf(aux[(size_t)row0 + tid] + coef + bcoef[0]);
    }
    __syncthreads();
    if (tid == 0) {
        float z = 0.f;
#pragma unroll
        for (int j = 0; j < 64; j++) z += wrow[j];
        g_zpart[blockIdx.x] = z;
    }

    // ---- epilogue 3: weighted column partials (reuse B smem region)
    float* part = (float*)(smc + OFF_B);   // [256 cols][20 stride], slots 0..15
    int slot = wm * 8 + gid;
    float w[2][2];
#pragma unroll
    for (int mf = 0; mf < 2; mf++)
#pragma unroll
        for (int rr = 0; rr < 2; rr++)
            w[mf][rr] = wrow[m0w + mf * 16 + rr * 8 + gid];
#pragma unroll
    for (int nf = 0; nf < 8; nf++) {
        int nl = n0w + nf * 8 + tig * 2;
        float p0 = 0.f, p1 = 0.f;
#pragma unroll
        for (int mf = 0; mf < 2; mf++)
#pragma unroll
            for (int rr = 0; rr < 2; rr++) {
                p0 += w[mf][rr] * acc[mf][nf][rr*2];
                p1 += w[mf][rr] * acc[mf][nf][rr*2+1];
            }
        part[nl * 20 + slot]       = p0;
        part[(nl + 1) * 20 + slot] = p1;
    }
    __syncthreads();
    {
        float s = 0.f;
#pragma unroll
        for (int q = 0; q < 16; q++) s += part[tid * 20 + q];
        g_part[(size_t)blockIdx.x * 256 + tid] = s;
    }
}

// ===========================================================================
// k_reduce: resid[bi][d] = sum_q S / sum_q Z   (deterministic fixed order)
__global__ void k_reduce() {
    int bi = blockIdx.x, d = threadIdx.x;
    float z = g_zpart[bi*4] + g_zpart[bi*4+1] + g_zpart[bi*4+2] + g_zpart[bi*4+3];
    float s = g_part[(size_t)(bi*4+0) * 256 + d] + g_part[(size_t)(bi*4+1) * 256 + d]
            + g_part[(size_t)(bi*4+2) * 256 + d] + g_part[(size_t)(bi*4+3) * 256 + d];
    g_resid[(size_t)bi * 256 + d] = s / z;
}

// ===========================================================================
// out: nodes + relu(resid @ W_out + b_out). BM=32 BN=64, grid (32,4)
__global__ void k_out(const float* __restrict__ nodes, const float* __restrict__ Wout,
                      const float* __restrict__ b_out, float* __restrict__ outn) {
    __shared__ float As[16][32];
    __shared__ float Bs[16][64];
    int tid = threadIdx.x;
    int tx = tid & 15, ty = tid >> 4;
    int row0 = blockIdx.x * 32;
    int n0   = blockIdx.y * 64;
    float c[2][4] = {};
    for (int k0 = 0; k0 < 256; k0 += 16) {
        {
            int f = tid;
            if (f < 128) {
                int r = f >> 2, kq = f & 3;
                float4 v = *(const float4*)&g_resid[(size_t)(row0 + r) * 256 + k0 + kq * 4];
                As[kq*4+0][r] = v.x; As[kq*4+1][r] = v.y; As[kq*4+2][r] = v.z; As[kq*4+3][r] = v.w;
            }
        }
        {
            int k = tid >> 4, nq = tid & 15;
            *(float4*)&Bs[k][nq*4] = *(const float4*)&Wout[(size_t)(k0 + k) * 256 + n0 + nq * 4];
        }
        __syncthreads();
#pragma unroll
        for (int k = 0; k < 16; k++) {
            float a0 = As[k][ty*2], a1 = As[k][ty*2+1];
            float bb[4];
            *(float4*)bb = *(float4*)&Bs[k][tx*4];
#pragma unroll
            for (int j = 0; j < 4; j++) { c[0][j] += a0 * bb[j]; c[1][j] += a1 * bb[j]; }
        }
        __syncthreads();
    }
#pragma unroll
    for (int i = 0; i < 2; i++) {
        int row = row0 + ty*2 + i;
#pragma unroll
        for (int j = 0; j < 4; j++) {
            int n = n0 + tx*4 + j;
            float v = fmaxf(c[i][j] + b_out[n], 0.f);
            outn[(size_t)row * 256 + n] = nodes[(size_t)row * 256 + n] + v;
        }
    }
}

// ===========================================================================
extern "C" void kernel_launch(void* const* d_in, const int* in_sizes, int n_in,
                              void* d_out, int out_size) {
    const float* nodes = (const float*)d_in[0];
    const float* edges = (const float*)d_in[1];
    const float* aux   = (const float*)d_in[2];
    // d_in[3] = nums (unused)
    const float* Win   = (const float*)d_in[4];
    const float* b_in  = (const float*)d_in[5];
    const float* Wcoef = (const float*)d_in[6];
    const float* bcoef = (const float*)d_in[7];
    const float* Wout  = (const float*)d_in[8];
    const float* b_out = (const float*)d_in[9];

    float* out_nodes = (float*)d_out;                    // [4,256,256]
    float* out_cat   = out_nodes + (size_t)BIv * Dv;     // [4,256,256,256]

    cudaFuncSetAttribute(k_main, cudaFuncAttributeMaxDynamicSharedMemorySize,
                         SMEM_MAIN_BYTES);

    k_prep   <<<256, 256>>>(Win);
    k_s12    <<<dim3(16, 8), 256>>>(nodes, Win, b_in);
    k_main   <<<4096, 256, SMEM_MAIN_BYTES>>>(edges, Wcoef, aux, bcoef, out_cat);
    k_reduce <<<1024, 256>>>();
    k_out    <<<dim3(32, 4), 256>>>(nodes, Wout, b_out, out_nodes);
}

// round 8
// speedup vs baseline: 1.2482x; 1.2482x over previous
#include <cuda_runtime.h>
#include <cuda_fp16.h>
#include <cstdint>
#include <cstring>

#define Bv 4
#define Nv 256
#define Dv 256
#define Mv (Bv*Nv*Nv)     // 262144 pair rows
#define BIv (Bv*Nv)       // 1024 (b,i) rows

// scratch (no allocations allowed)
__device__ __align__(16) float g_s12[BIv * 512];     // s1 (cols 0..255), s2+b_in (cols 256..511)
__device__ __align__(16) float g_coef[Mv];           // per-row coef logits (pre-bias)
__device__ __align__(16) float g_resid[BIv * Dv];
// W_in[512:768,:] fp16, layout [c32][kg16][n][16perm]
__device__ __align__(16) __half g_w3h[256 * 256];

__device__ __forceinline__ uint32_t smem_u32(const void* p) {
    uint32_t a;
    asm("{ .reg .u64 t; cvta.to.shared.u64 t, %1; cvt.u32.u64 %0, t; }" : "=r"(a) : "l"(p));
    return a;
}
__device__ __forceinline__ uint32_t f2h2(float a, float b) {
    __half2 h = __floats2half2_rn(a, b);
    uint32_t u; memcpy(&u, &h, 4); return u;
}
__device__ __forceinline__ void mma_f16(float* d, const uint32_t* a, const uint32_t* b) {
    asm volatile(
        "mma.sync.aligned.m16n8k16.row.col.f32.f16.f16.f32 "
        "{%0,%1,%2,%3}, {%4,%5,%6,%7}, {%8,%9}, {%0,%1,%2,%3};"
        : "+f"(d[0]), "+f"(d[1]), "+f"(d[2]), "+f"(d[3])
        : "r"(a[0]), "r"(a[1]), "r"(a[2]), "r"(a[3]), "r"(b[0]), "r"(b[1]));
}
__device__ __forceinline__ void ldsm4(uint32_t* r, uint32_t addr) {
    asm volatile("ldmatrix.sync.aligned.m8n8.x4.shared.b16 {%0,%1,%2,%3}, [%4];"
        : "=r"(r[0]), "=r"(r[1]), "=r"(r[2]), "=r"(r[3]) : "r"(addr));
}
#define CP_ASYNC16(s, g) \
    asm volatile("cp.async.ca.shared.global [%0], [%1], 16;" :: "r"(s), "l"(g))
#define CP_COMMIT()  asm volatile("cp.async.commit_group;" ::: "memory")
#define CP_WAIT0()   asm volatile("cp.async.wait_group 0;" ::: "memory")
#define CP_WAIT1()   asm volatile("cp.async.wait_group 1;" ::: "memory")

// ===========================================================================
// k_prep: fp16 permuted copy of W_in[512:768,:]
__global__ void k_prep(const float* __restrict__ Win) {
    int k = blockIdx.x, n = threadIdx.x;
    int c = k >> 5, kg = (k >> 4) & 1, kk = k & 15;
    int t = (kk & 7) >> 1;
    int u = (kk & 1) + ((kk >> 3) << 1);
    int p = t * 4 + u;
    g_w3h[(((size_t)(c * 2 + kg)) * 256 + n) * 16 + p] =
        __float2half_rn(Win[(size_t)(512 + k) * 256 + n]);
}

// ===========================================================================
// s12: [1024,256] (nodes) @ W_in[0:512,:] -> g_s12 [1024,512] (fp32 exact)
__global__ void k_s12(const float* __restrict__ nodes, const float* __restrict__ Win,
                      const float* __restrict__ b_in) {
    __shared__ float As[16][64];
    __shared__ float Bs[16][64];
    int tid = threadIdx.x;
    int tx = tid & 15, ty = tid >> 4;
    int row0 = blockIdx.x * 64;
    int n0   = blockIdx.y * 64;
    float c[4][4] = {};
    for (int k0 = 0; k0 < 256; k0 += 16) {
        {
            int r = tid >> 2, kq = tid & 3;
            float4 v = *(const float4*)&nodes[(size_t)(row0 + r) * 256 + k0 + kq * 4];
            As[kq*4+0][r] = v.x; As[kq*4+1][r] = v.y; As[kq*4+2][r] = v.z; As[kq*4+3][r] = v.w;
        }
        {
            int k = tid >> 4, nq = tid & 15;
            int n = n0 + nq * 4;
            const float* src = (n < 256) ? &Win[(size_t)(k0 + k) * 256 + n]
                                         : &Win[(size_t)(256 + k0 + k) * 256 + (n - 256)];
            *(float4*)&Bs[k][nq*4] = *(const float4*)src;
        }
        __syncthreads();
#pragma unroll
        for (int k = 0; k < 16; k++) {
            float a[4], b[4];
            *(float4*)a = *(float4*)&As[k][ty*4];
            *(float4*)b = *(float4*)&Bs[k][tx*4];
#pragma unroll
            for (int i = 0; i < 4; i++)
#pragma unroll
                for (int j = 0; j < 4; j++) c[i][j] += a[i] * b[j];
        }
        __syncthreads();
    }
#pragma unroll
    for (int i = 0; i < 4; i++) {
        int row = row0 + ty*4 + i;
#pragma unroll
        for (int j = 0; j < 4; j++) {
            int n = n0 + tx*4 + j;
            float v = c[i][j] + (n >= 256 ? b_in[n - 256] : 0.f);
            g_s12[(size_t)row * 512 + n] = v;
        }
    }
}

// ===========================================================================
// k_main: fp16 mma m16n8k16, BM=64 x BN=256 x BK=64 (4 chunks, 4 syncs),
// 256 thr (2M x 4N warps). A: LDG->cvt->STS 2-stage halves; B: cp.async 2-stage.
#define A_STG_B 9216                     // 64 rows x 144B (64 halves + 16B pad)
#define B_STG_B 32768                    // 64k x 256n x 2B
#define OFF_A    0                       // 2 stages: 18432
#define OFF_B    18432                   // 2 stages: 65536
#define OFF_S1   83968
#define OFF_WC   84992
#define OFF_RED  86016                   // 64*4 floats
#define SMEM_MAIN_BYTES 87040

__global__ void __launch_bounds__(256, 2) k_main(const float* __restrict__ edges,
                                                 const float* __restrict__ Wcoef,
                                                 float* __restrict__ cat) {
    extern __shared__ __align__(128) char smc[];
    float* s1s = (float*)(smc + OFF_S1);
    float* wcs = (float*)(smc + OFF_WC);
    float* red = (float*)(smc + OFF_RED);

    int tid = threadIdx.x;
    int lane = tid & 31, wid = tid >> 5;
    int gid = lane >> 2, tig = lane & 3;
    int wm = wid & 1, wn = wid >> 1;
    int m0w = wm * 32, n0w = wn * 64;

    int row0 = blockIdx.x * 64;
    int bi = row0 >> 8;
    int b  = bi >> 8;

    s1s[tid] = g_s12[(size_t)bi * 512 + tid];
    wcs[tid] = Wcoef[tid];

    // A mapping: row = tid>>2, 8-float segment aj within a 32-float half
    int ar = tid >> 2, aj = tid & 3;
    const float* a_src = &edges[(size_t)(row0 + ar) * 256 + aj * 8];
    uint32_t a_sts = smem_u32(smc + OFF_A) + (uint32_t)(ar * 144 + aj * 16);

    uint32_t b_smem = smem_u32(smc + OFF_B);
    const char* b_gbase = (const char*)g_w3h;

    float4 rb[2];
    int lrow = ((lane >> 3) & 1) * 8 + (lane & 7);
    int lkb  = (lane >> 4) * 16;

    // LDGA(c,h): load 8 floats of half h (k in [c*64+h*32, +32))
#define LDGA(c, h) do { \
        rb[0] = *(const float4*)(a_src + (c) * 64 + (h) * 32); \
        rb[1] = *(const float4*)(a_src + (c) * 64 + (h) * 32 + 4); } while (0)
#define STSA(c, h) do { \
        uint4 t_; \
        t_.x = f2h2(rb[0].x, rb[0].y); \
        t_.y = f2h2(rb[0].z, rb[0].w); \
        t_.z = f2h2(rb[1].x, rb[1].y); \
        t_.w = f2h2(rb[1].z, rb[1].w); \
        asm volatile("st.shared.v4.b32 [%0], {%1,%2,%3,%4};" \
            :: "r"(a_sts + ((c) & 1) * A_STG_B + (h) * 64), \
               "r"(t_.x), "r"(t_.y), "r"(t_.z), "r"(t_.w) : "memory"); } while (0)
    // CPB(c): copy 32KB B chunk (k in [c*64, +64)) into stage c&1
#define CPB(c) do { \
        _Pragma("unroll") \
        for (int i_ = 0; i_ < 8; i_++) { \
            int u_ = tid + i_ * 256; \
            int sub_ = u_ >> 10, rem_ = u_ & 1023; \
            int kg_ = rem_ >> 9, n_ = (rem_ >> 1) & 255, h_ = rem_ & 1; \
            uint32_t d_ = b_smem + ((c) & 1) * B_STG_B + sub_ * 16384 + kg_ * 8192 \
                        + n_ * 32 + h_ * 16; \
            const void* s_ = b_gbase + (((size_t)((c) * 4 + sub_ * 2 + kg_)) * 256 + n_) * 32 \
                           + h_ * 16; \
            CP_ASYNC16(d_, s_); \
        } } while (0)

    // MMA for one k16 step ks (0..3) of chunk stage cs
#define MMA_KS(cs, ks) do { \
        uint32_t aBase_ = smem_u32(smc + OFF_A) + (cs) * A_STG_B; \
        const char* Bs_ = smc + OFF_B + (cs) * B_STG_B + ((ks) >> 1) * 16384 \
                        + ((ks) & 1) * 8192; \
        uint32_t a_[2][4]; \
        _Pragma("unroll") \
        for (int mf_ = 0; mf_ < 2; mf_++) \
            ldsm4(a_[mf_], aBase_ + (uint32_t)((m0w + mf_ * 16 + lrow) * 144 \
                  + (ks) * 32 + lkb)); \
        uint32_t bf_[8][2]; \
        _Pragma("unroll") \
        for (int nf_ = 0; nf_ < 8; nf_++) { \
            int n_ = n0w + nf_ * 8 + gid; \
            uint2 pv_ = *(const uint2*)(Bs_ + n_ * 32 + tig * 8); \
            bf_[nf_][0] = pv_.x; bf_[nf_][1] = pv_.y; \
        } \
        _Pragma("unroll") \
        for (int mf_ = 0; mf_ < 2; mf_++) \
            _Pragma("unroll") \
            for (int nf_ = 0; nf_ < 8; nf_++) \
                mma_f16(acc[mf_][nf_], a_[mf_], bf_[nf_]); } while (0)

    // ---- prologue: B chunks 0,1 in flight; A chunk 0 staged
    CPB(0); CP_COMMIT();
    CPB(1); CP_COMMIT();
    LDGA(0, 0); STSA(0, 0);
    LDGA(0, 1); STSA(0, 1);
    CP_WAIT1();                   // B chunk 0 ready
    __syncthreads();

    float acc[2][8][4] = {};

#pragma unroll
    for (int c = 0; c < 4; c++) {
        int cs = c & 1;
        if (c >= 1 && c + 1 < 4) { CPB(c + 1); }   // B stage (c+1)&1 freed at last sync
        CP_COMMIT();
        if (c + 1 < 4) LDGA(c + 1, 0);
        MMA_KS(cs, 0);
        MMA_KS(cs, 1);
        if (c + 1 < 4) { STSA(c + 1, 0); LDGA(c + 1, 1); }
        MMA_KS(cs, 2);
        MMA_KS(cs, 3);
        if (c + 1 < 4) STSA(c + 1, 1);
        CP_WAIT0();
        __syncthreads();
    }

    // ---- epilogue: add s1/s2, relu, store cat, coef partials
#pragma unroll
    for (int mf = 0; mf < 2; mf++) {
#pragma unroll
        for (int rr = 0; rr < 2; rr++) {
            int row_local = m0w + mf * 16 + gid + rr * 8;
            int m  = row0 + row_local;
            int jj = (row0 & 255) + row_local;
            const float* s2p = &g_s12[((size_t)(b * 256 + jj)) * 512 + 256];
            float* catp = &cat[(size_t)m * 256];
            float csum = 0.f;
#pragma unroll
            for (int nf = 0; nf < 8; nf++) {
                int nl = n0w + nf * 8 + tig * 2;
                float v0 = acc[mf][nf][rr*2]   + s1s[nl]   + s2p[nl];
                float v1 = acc[mf][nf][rr*2+1] + s1s[nl+1] + s2p[nl+1];
                v0 = fmaxf(v0, 0.f); v1 = fmaxf(v1, 0.f);
                csum += v0 * wcs[nl] + v1 * wcs[nl + 1];
                float2 st = { v0, v1 };
                *(float2*)&catp[nl] = st;
            }
            csum += __shfl_xor_sync(0xffffffffu, csum, 1);
            csum += __shfl_xor_sync(0xffffffffu, csum, 2);
            if (tig == 0) red[row_local * 4 + wn] = csum;
        }
    }
    __syncthreads();
    if (tid < 64) {
        float s = red[tid*4] + red[tid*4+1] + red[tid*4+2] + red[tid*4+3];
        g_coef[row0 + tid] = s;
    }
}

// ===========================================================================
// softmax over neighbors + weighted sum -> g_resid. block = (b,i), 256 threads.
// Weighted sum: 4 j-groups x 64 col-threads, float4 per thread, smem reduce.
__global__ void k_softmax(const float* __restrict__ aux, const float* __restrict__ bcoef,
                          const float* __restrict__ cat) {
    __shared__ float attn[256];
    __shared__ float part[4 * 256];
    __shared__ float redbuf[8];
    int bi = blockIdx.x;
    int tid = threadIdx.x;
    size_t row = (size_t)bi * 256 + tid;
    float logit = aux[row] + g_coef[row] + bcoef[0];

    float v = logit;
#pragma unroll
    for (int o = 16; o > 0; o >>= 1) v = fmaxf(v, __shfl_xor_sync(0xffffffffu, v, o));
    if ((tid & 31) == 0) redbuf[tid >> 5] = v;
    __syncthreads();
    float mx = redbuf[0];
#pragma unroll
    for (int i = 1; i < 8; i++) mx = fmaxf(mx, redbuf[i]);

    float e = expf(logit - mx);
    v = e;
#pragma unroll
    for (int o = 16; o > 0; o >>= 1) v += __shfl_xor_sync(0xffffffffu, v, o);
    __syncthreads();
    if ((tid & 31) == 0) redbuf[tid >> 5] = v;
    __syncthreads();
    float s = 0.f;
#pragma unroll
    for (int i = 0; i < 8; i++) s += redbuf[i];
    attn[tid] = e / s;
    __syncthreads();

    int grp  = tid >> 6;                 // 0..3: j stride group
    int colb = (tid & 63) * 4;           // column base
    const float* base = &cat[(size_t)bi * 65536 + colb];
    float a0 = 0.f, a1 = 0.f, a2 = 0.f, a3 = 0.f;
#pragma unroll 4
    for (int j = grp; j < 256; j += 4) {
        float w = attn[j];
        float4 vv = *(const float4*)(base + (size_t)j * 256);
        a0 += w * vv.x; a1 += w * vv.y; a2 += w * vv.z; a3 += w * vv.w;
    }
    float* pp = &part[grp * 256 + colb];
    pp[0] = a0; pp[1] = a1; pp[2] = a2; pp[3] = a3;
    __syncthreads();
    {
        float r = part[tid] + part[256 + tid] + part[512 + tid] + part[768 + tid];
        g_resid[row] = r;
    }
}

// ===========================================================================
// out: nodes + relu(resid @ W_out + b_out). BM=32 BN=64, grid (32,4)
__global__ void k_out(const float* __restrict__ nodes, const float* __restrict__ Wout,
                      const float* __restrict__ b_out, float* __restrict__ outn) {
    __shared__ float As[16][32];
    __shared__ float Bs[16][64];
    int tid = threadIdx.x;
    int tx = tid & 15, ty = tid >> 4;
    int row0 = blockIdx.x * 32;
    int n0   = blockIdx.y * 64;
    float c[2][4] = {};
    for (int k0 = 0; k0 < 256; k0 += 16) {
        {
            int f = tid;
            if (f < 128) {
                int r = f >> 2, kq = f & 3;
                float4 v = *(const float4*)&g_resid[(size_t)(row0 + r) * 256 + k0 + kq * 4];
                As[kq*4+0][r] = v.x; As[kq*4+1][r] = v.y; As[kq*4+2][r] = v.z; As[kq*4+3][r] = v.w;
            }
        }
        {
            int k = tid >> 4, nq = tid & 15;
            *(float4*)&Bs[k][nq*4] = *(const float4*)&Wout[(size_t)(k0 + k) * 256 + n0 + nq * 4];
        }
        __syncthreads();
#pragma unroll
        for (int k = 0; k < 16; k++) {
            float a0 = As[k][ty*2], a1 = As[k][ty*2+1];
            float bb[4];
            *(float4*)bb = *(float4*)&Bs[k][tx*4];
#pragma unroll
            for (int j = 0; j < 4; j++) { c[0][j] += a0 * bb[j]; c[1][j] += a1 * bb[j]; }
        }
        __syncthreads();
    }
#pragma unroll
    for (int i = 0; i < 2; i++) {
        int row = row0 + ty*2 + i;
#pragma unroll
        for (int j = 0; j < 4; j++) {
            int n = n0 + tx*4 + j;
            float v = fmaxf(c[i][j] + b_out[n], 0.f);
            outn[(size_t)row * 256 + n] = nodes[(size_t)row * 256 + n] + v;
        }
    }
}

// ===========================================================================
extern "C" void kernel_launch(void* const* d_in, const int* in_sizes, int n_in,
                              void* d_out, int out_size) {
    const float* nodes = (const float*)d_in[0];
    const float* edges = (const float*)d_in[1];
    const float* aux   = (const float*)d_in[2];
    // d_in[3] = nums (unused)
    const float* Win   = (const float*)d_in[4];
    const float* b_in  = (const float*)d_in[5];
    const float* Wcoef = (const float*)d_in[6];
    const float* bcoef = (const float*)d_in[7];
    const float* Wout  = (const float*)d_in[8];
    const float* b_out = (const float*)d_in[9];

    float* out_nodes = (float*)d_out;                    // [4,256,256]
    float* out_cat   = out_nodes + (size_t)BIv * Dv;     // [4,256,256,256]

    cudaFuncSetAttribute(k_main, cudaFuncAttributeMaxDynamicSharedMemorySize,
                         SMEM_MAIN_BYTES);

    k_prep   <<<256, 256>>>(Win);
    k_s12    <<<dim3(16, 8), 256>>>(nodes, Win, b_in);
    k_main   <<<4096, 256, SMEM_MAIN_BYTES>>>(edges, Wcoef, out_cat);
    k_softmax<<<1024, 256>>>(aux, bcoef, out_cat);
    k_out    <<<dim3(32, 4), 256>>>(nodes, Wout, b_out, out_nodes);
}

// round 9
// speedup vs baseline: 1.3673x; 1.0954x over previous
#include <cuda_runtime.h>
#include <cuda_fp16.h>
#include <cstdint>
#include <cstring>

#define Bv 4
#define Nv 256
#define Dv 256
#define Mv (Bv*Nv*Nv)     // 262144 pair rows
#define BIv (Bv*Nv)       // 1024 (b,i) rows

// scratch (no allocations allowed)
__device__ __align__(16) float g_s12[BIv * 512];     // s1 (cols 0..255), s2+b_in (cols 256..511)
__device__ __align__(16) float g_resid[BIv * Dv];
__device__ __align__(16) float g_part[4096 * 256];   // per-CTA weighted column partials
__device__ __align__(16) float g_zpart[4096];        // per-CTA exp-sum partials
// W_in[512:768,:] fp16, layout [c32][kg16][n][16perm]
__device__ __align__(16) __half g_w3h[256 * 256];

__device__ __forceinline__ uint32_t smem_u32(const void* p) {
    uint32_t a;
    asm("{ .reg .u64 t; cvta.to.shared.u64 t, %1; cvt.u32.u64 %0, t; }" : "=r"(a) : "l"(p));
    return a;
}
__device__ __forceinline__ uint32_t f2h2(float a, float b) {
    __half2 h = __floats2half2_rn(a, b);
    uint32_t u; memcpy(&u, &h, 4); return u;
}
__device__ __forceinline__ void mma_f16(float* d, const uint32_t* a, const uint32_t* b) {
    asm volatile(
        "mma.sync.aligned.m16n8k16.row.col.f32.f16.f16.f32 "
        "{%0,%1,%2,%3}, {%4,%5,%6,%7}, {%8,%9}, {%0,%1,%2,%3};"
        : "+f"(d[0]), "+f"(d[1]), "+f"(d[2]), "+f"(d[3])
        : "r"(a[0]), "r"(a[1]), "r"(a[2]), "r"(a[3]), "r"(b[0]), "r"(b[1]));
}
__device__ __forceinline__ void ldsm4(uint32_t* r, uint32_t addr) {
    asm volatile("ldmatrix.sync.aligned.m8n8.x4.shared.b16 {%0,%1,%2,%3}, [%4];"
        : "=r"(r[0]), "=r"(r[1]), "=r"(r[2]), "=r"(r[3]) : "r"(addr));
}
#define CP_ASYNC16(s, g) \
    asm volatile("cp.async.ca.shared.global [%0], [%1], 16;" :: "r"(s), "l"(g))
#define CP_COMMIT()  asm volatile("cp.async.commit_group;" ::: "memory")
#define CP_WAIT1()   asm volatile("cp.async.wait_group 1;" ::: "memory")

// ===========================================================================
// k_prep: fp16 permuted copy of W_in[512:768,:]
__global__ void k_prep(const float* __restrict__ Win) {
    int k = blockIdx.x, n = threadIdx.x;
    int c = k >> 5, kg = (k >> 4) & 1, kk = k & 15;
    int t = (kk & 7) >> 1;
    int u = (kk & 1) + ((kk >> 3) << 1);
    int p = t * 4 + u;
    g_w3h[(((size_t)(c * 2 + kg)) * 256 + n) * 16 + p] =
        __float2half_rn(Win[(size_t)(512 + k) * 256 + n]);
}

// ===========================================================================
// s12: [1024,256] (nodes) @ W_in[0:512,:] -> g_s12 [1024,512] (fp32 exact)
__global__ void k_s12(const float* __restrict__ nodes, const float* __restrict__ Win,
                      const float* __restrict__ b_in) {
    __shared__ float As[16][64];
    __shared__ float Bs[16][64];
    int tid = threadIdx.x;
    int tx = tid & 15, ty = tid >> 4;
    int row0 = blockIdx.x * 64;
    int n0   = blockIdx.y * 64;
    float c[4][4] = {};
    for (int k0 = 0; k0 < 256; k0 += 16) {
        {
            int r = tid >> 2, kq = tid & 3;
            float4 v = *(const float4*)&nodes[(size_t)(row0 + r) * 256 + k0 + kq * 4];
            As[kq*4+0][r] = v.x; As[kq*4+1][r] = v.y; As[kq*4+2][r] = v.z; As[kq*4+3][r] = v.w;
        }
        {
            int k = tid >> 4, nq = tid & 15;
            int n = n0 + nq * 4;
            const float* src = (n < 256) ? &Win[(size_t)(k0 + k) * 256 + n]
                                         : &Win[(size_t)(256 + k0 + k) * 256 + (n - 256)];
            *(float4*)&Bs[k][nq*4] = *(const float4*)src;
        }
        __syncthreads();
#pragma unroll
        for (int k = 0; k < 16; k++) {
            float a[4], b[4];
            *(float4*)a = *(float4*)&As[k][ty*4];
            *(float4*)b = *(float4*)&Bs[k][tx*4];
#pragma unroll
            for (int i = 0; i < 4; i++)
#pragma unroll
                for (int j = 0; j < 4; j++) c[i][j] += a[i] * b[j];
        }
        __syncthreads();
    }
#pragma unroll
    for (int i = 0; i < 4; i++) {
        int row = row0 + ty*4 + i;
#pragma unroll
        for (int j = 0; j < 4; j++) {
            int n = n0 + tx*4 + j;
            float v = c[i][j] + (n >= 256 ? b_in[n - 256] : 0.f);
            g_s12[(size_t)row * 512 + n] = v;
        }
    }
}

// ===========================================================================
// k_main: fp16 mma m16n8k16, BM=64 x BN=256 x BK=32, 256 thr (R6 mainloop).
// Epilogue: cat store + smem tile copy; then softmax partials from the tile
// (acc registers die in epilogue-1 -> no extra register pressure).
#define A_STG_B 5120                     // 64 rows x 80B
#define B_STG_B 16384                    // 32k x 256n x 2B
#define TSTR    264                      // epilogue tile stride (floats)
#define OFF_A    0                       // 2 stages: 10240
#define OFF_B    10240                   // union: 3 B stages (49152) / tile (64*264*4=67584)
#define OFF_S1   77824
#define OFF_WC   78848
#define OFF_RED  79872                   // 64*4 floats
#define OFF_WROW 80896                   // 64 floats
#define SMEM_MAIN_BYTES 81152

__global__ void __launch_bounds__(256, 2) k_main(const float* __restrict__ edges,
                                                 const float* __restrict__ Wcoef,
                                                 const float* __restrict__ aux,
                                                 const float* __restrict__ bcoef,
                                                 float* __restrict__ cat) {
    extern __shared__ __align__(128) char smc[];
    float* s1s  = (float*)(smc + OFF_S1);
    float* wcs  = (float*)(smc + OFF_WC);
    float* red  = (float*)(smc + OFF_RED);
    float* wrow = (float*)(smc + OFF_WROW);
    float* tile = (float*)(smc + OFF_B);   // valid after mainloop (B stages dead)

    int tid = threadIdx.x;
    int lane = tid & 31, wid = tid >> 5;
    int gid = lane >> 2, tig = lane & 3;
    int wm = wid & 1, wn = wid >> 1;
    int m0w = wm * 32, n0w = wn * 64;

    int row0 = blockIdx.x * 64;
    int bi = row0 >> 8;
    int b  = bi >> 8;

    s1s[tid] = g_s12[(size_t)bi * 512 + tid];
    wcs[tid] = Wcoef[tid];

    int ar = tid >> 2, aj = tid & 3;
    const float* a_src = &edges[(size_t)(row0 + ar) * 256 + aj * 8];
    uint32_t a_sts = smem_u32(smc + OFF_A) + (uint32_t)(ar * 80 + aj * 16);

    uint32_t b_smem = smem_u32(smc + OFF_B);
    const char* b_gbase = (const char*)g_w3h;

    float4 rb[2][2];
    int lrow = ((lane >> 3) & 1) * 8 + (lane & 7);
    int lkb  = (lane >> 4) * 16;

#define LDGA(c, bf) do { \
        rb[bf][0] = *(const float4*)(a_src + (c) * 32); \
        rb[bf][1] = *(const float4*)(a_src + (c) * 32 + 4); } while (0)
#define STSA(c, bf) do { \
        uint4 t_; \
        t_.x = f2h2(rb[bf][0].x, rb[bf][0].y); \
        t_.y = f2h2(rb[bf][0].z, rb[bf][0].w); \
        t_.z = f2h2(rb[bf][1].x, rb[bf][1].y); \
        t_.w = f2h2(rb[bf][1].z, rb[bf][1].w); \
        asm volatile("st.shared.v4.b32 [%0], {%1,%2,%3,%4};" \
            :: "r"(a_sts + ((c) & 1) * A_STG_B), "r"(t_.x), "r"(t_.y), "r"(t_.z), "r"(t_.w) \
            : "memory"); } while (0)
#define CPB(c) do { \
        int s3_ = (c) - ((c) / 3) * 3; \
        _Pragma("unroll") \
        for (int i_ = 0; i_ < 4; i_++) { \
            int u_ = tid + i_ * 256; \
            int kg_ = u_ >> 9, n_ = (u_ >> 1) & 255, h_ = u_ & 1; \
            uint32_t d_ = b_smem + s3_ * B_STG_B + kg_ * 8192 + n_ * 32 + h_ * 16; \
            const void* s_ = b_gbase + (((size_t)((c) * 2 + kg_)) * 256 + n_) * 32 + h_ * 16; \
            CP_ASYNC16(d_, s_); \
        } } while (0)

    // ---- prologue
    LDGA(0, 0); LDGA(1, 1);
    CPB(0); CP_COMMIT();
    CPB(1); CP_COMMIT();
    STSA(0, 0);
    CP_WAIT1();
    __syncthreads();

    float acc[2][8][4] = {};

#pragma unroll
    for (int c = 0; c < 8; c++) {
        if (c + 2 < 8) CPB(c + 2);
        CP_COMMIT();
        if (c + 1 < 8) STSA(c + 1, (c + 1) & 1);
        if (c + 2 < 8) LDGA(c + 2, c & 1);

        uint32_t aBase = smem_u32(smc + OFF_A) + (c & 1) * A_STG_B;
        const char* Bs_ = smc + OFF_B + (c - (c / 3) * 3) * B_STG_B;
#pragma unroll
        for (int ks = 0; ks < 2; ks++) {
            uint32_t a[2][4];
#pragma unroll
            for (int mf = 0; mf < 2; mf++)
                ldsm4(a[mf], aBase + (uint32_t)((m0w + mf * 16 + lrow) * 80 + ks * 32 + lkb));
            uint32_t bf[8][2];
#pragma unroll
            for (int nf = 0; nf < 8; nf++) {
                int n = n0w + nf * 8 + gid;
                uint2 pv = *(const uint2*)(Bs_ + ks * 8192 + n * 32 + tig * 8);
                bf[nf][0] = pv.x; bf[nf][1] = pv.y;
            }
#pragma unroll
            for (int mf = 0; mf < 2; mf++)
#pragma unroll
                for (int nf = 0; nf < 8; nf++)
                    mma_f16(acc[mf][nf], a[mf], bf[nf]);
        }
        CP_WAIT1();
        __syncthreads();
    }

    // ---- epilogue 1: add s1/s2, relu, store cat (gmem) + tile (smem), coef
#pragma unroll
    for (int mf = 0; mf < 2; mf++) {
#pragma unroll
        for (int rr = 0; rr < 2; rr++) {
            int row_local = m0w + mf * 16 + gid + rr * 8;
            int m  = row0 + row_local;
            int jj = (row0 & 255) + row_local;
            const float* s2p = &g_s12[((size_t)(b * 256 + jj)) * 512 + 256];
            float* catp  = &cat[(size_t)m * 256];
            float* tilep = &tile[(size_t)row_local * TSTR];
            float csum = 0.f;
#pragma unroll
            for (int nf = 0; nf < 8; nf++) {
                int nl = n0w + nf * 8 + tig * 2;
                float v0 = acc[mf][nf][rr*2]   + s1s[nl]   + s2p[nl];
                float v1 = acc[mf][nf][rr*2+1] + s1s[nl+1] + s2p[nl+1];
                v0 = fmaxf(v0, 0.f); v1 = fmaxf(v1, 0.f);
                csum += v0 * wcs[nl] + v1 * wcs[nl + 1];
                float2 st = { v0, v1 };
                *(float2*)&catp[nl]  = st;
                *(float2*)&tilep[nl] = st;
            }
            csum += __shfl_xor_sync(0xffffffffu, csum, 1);
            csum += __shfl_xor_sync(0xffffffffu, csum, 2);
            if (tig == 0) red[row_local * 4 + wn] = csum;
        }
    }
    __syncthreads();

    // ---- epilogue 2: w_j = exp(aux + coef + bc)
    if (tid < 64) {
        float coef = red[tid*4] + red[tid*4+1] + red[tid*4+2] + red[tid*4+3];
        wrow[tid] = __expf(aux[(size_t)row0 + tid] + coef + bcoef[0]);
    }
    __syncthreads();
    if (tid == 0) {
        float z = 0.f;
#pragma unroll
        for (int j = 0; j < 64; j++) z += wrow[j];
        g_zpart[blockIdx.x] = z;
    }

    // ---- epilogue 3: weighted column sums from the smem tile
    {
        float S = 0.f;
#pragma unroll 8
        for (int j = 0; j < 64; j++) S += wrow[j] * tile[(size_t)j * TSTR + tid];
        g_part[(size_t)blockIdx.x * 256 + tid] = S;
    }
}

// ===========================================================================
// k_reduce: resid[bi][d] = sum_q S / sum_q Z   (deterministic fixed order)
__global__ void k_reduce() {
    int bi = blockIdx.x, d = threadIdx.x;
    float z = g_zpart[bi*4] + g_zpart[bi*4+1] + g_zpart[bi*4+2] + g_zpart[bi*4+3];
    float s = g_part[(size_t)(bi*4+0) * 256 + d] + g_part[(size_t)(bi*4+1) * 256 + d]
            + g_part[(size_t)(bi*4+2) * 256 + d] + g_part[(size_t)(bi*4+3) * 256 + d];
    g_resid[(size_t)bi * 256 + d] = s / z;
}

// ===========================================================================
// out: nodes + relu(resid @ W_out + b_out). BM=32 BN=64, grid (32,4)
__global__ void k_out(const float* __restrict__ nodes, const float* __restrict__ Wout,
                      const float* __restrict__ b_out, float* __restrict__ outn) {
    __shared__ float As[16][32];
    __shared__ float Bs[16][64];
    int tid = threadIdx.x;
    int tx = tid & 15, ty = tid >> 4;
    int row0 = blockIdx.x * 32;
    int n0   = blockIdx.y * 64;
    float c[2][4] = {};
    for (int k0 = 0; k0 < 256; k0 += 16) {
        {
            int f = tid;
            if (f < 128) {
                int r = f >> 2, kq = f & 3;
                float4 v = *(const float4*)&g_resid[(size_t)(row0 + r) * 256 + k0 + kq * 4];
                As[kq*4+0][r] = v.x; As[kq*4+1][r] = v.y; As[kq*4+2][r] = v.z; As[kq*4+3][r] = v.w;
            }
        }
        {
            int k = tid >> 4, nq = tid & 15;
            *(float4*)&Bs[k][nq*4] = *(const float4*)&Wout[(size_t)(k0 + k) * 256 + n0 + nq * 4];
        }
        __syncthreads();
#pragma unroll
        for (int k = 0; k < 16; k++) {
            float a0 = As[k][ty*2], a1 = As[k][ty*2+1];
            float bb[4];
            *(float4*)bb = *(float4*)&Bs[k][tx*4];
#pragma unroll
            for (int j = 0; j < 4; j++) { c[0][j] += a0 * bb[j]; c[1][j] += a1 * bb[j]; }
        }
        __syncthreads();
    }
#pragma unroll
    for (int i = 0; i < 2; i++) {
        int row = row0 + ty*2 + i;
#pragma unroll
        for (int j = 0; j < 4; j++) {
            int n = n0 + tx*4 + j;
            float v = fmaxf(c[i][j] + b_out[n], 0.f);
            outn[(size_t)row * 256 + n] = nodes[(size_t)row * 256 + n] + v;
        }
    }
}

// ===========================================================================
extern "C" void kernel_launch(void* const* d_in, const int* in_sizes, int n_in,
                              void* d_out, int out_size) {
    const float* nodes = (const float*)d_in[0];
    const float* edges = (const float*)d_in[1];
    const float* aux   = (const float*)d_in[2];
    // d_in[3] = nums (unused)
    const float* Win   = (const float*)d_in[4];
    const float* b_in  = (const float*)d_in[5];
    const float* Wcoef = (const float*)d_in[6];
    const float* bcoef = (const float*)d_in[7];
    const float* Wout  = (const float*)d_in[8];
    const float* b_out = (const float*)d_in[9];

    float* out_nodes = (float*)d_out;                    // [4,256,256]
    float* out_cat   = out_nodes + (size_t)BIv * Dv;     // [4,256,256,256]

    cudaFuncSetAttribute(k_main, cudaFuncAttributeMaxDynamicSharedMemorySize,
                         SMEM_MAIN_BYTES);

    k_prep   <<<256, 256>>>(Win);
    k_s12    <<<dim3(16, 8), 256>>>(nodes, Win, b_in);
    k_main   <<<4096, 256, SMEM_MAIN_BYTES>>>(edges, Wcoef, aux, bcoef, out_cat);
    k_reduce <<<1024, 256>>>();
    k_out    <<<dim3(32, 4), 256>>>(nodes, Wout, b_out, out_nodes);
}

// round 10
// speedup vs baseline: 1.4900x; 1.0898x over previous
#include <cuda_runtime.h>
#include <cuda_fp16.h>
#include <cstdint>
#include <cstring>

#define Bv 4
#define Nv 256
#define Dv 256
#define Mv (Bv*Nv*Nv)     // 262144 pair rows
#define BIv (Bv*Nv)       // 1024 (b,i) rows

// scratch (no allocations allowed)
__device__ __align__(16) float g_s12[BIv * 512];     // s1 (cols 0..255), s2+b_in (cols 256..511)
__device__ __align__(16) float g_part[4096 * 256];   // per-CTA weighted column partials
__device__ __align__(16) float g_zpart[4096];        // per-CTA exp-sum partials
// W_in[512:768,:] fp16, layout [c32][kg16][n][16perm]
__device__ __align__(16) __half g_w3h[256 * 256];

__device__ __forceinline__ uint32_t smem_u32(const void* p) {
    uint32_t a;
    asm("{ .reg .u64 t; cvta.to.shared.u64 t, %1; cvt.u32.u64 %0, t; }" : "=r"(a) : "l"(p));
    return a;
}
__device__ __forceinline__ uint32_t f2h2(float a, float b) {
    __half2 h = __floats2half2_rn(a, b);
    uint32_t u; memcpy(&u, &h, 4); return u;
}
__device__ __forceinline__ void mma_f16(float* d, const uint32_t* a, const uint32_t* b) {
    asm volatile(
        "mma.sync.aligned.m16n8k16.row.col.f32.f16.f16.f32 "
        "{%0,%1,%2,%3}, {%4,%5,%6,%7}, {%8,%9}, {%0,%1,%2,%3};"
        : "+f"(d[0]), "+f"(d[1]), "+f"(d[2]), "+f"(d[3])
        : "r"(a[0]), "r"(a[1]), "r"(a[2]), "r"(a[3]), "r"(b[0]), "r"(b[1]));
}
__device__ __forceinline__ void ldsm4(uint32_t* r, uint32_t addr) {
    asm volatile("ldmatrix.sync.aligned.m8n8.x4.shared.b16 {%0,%1,%2,%3}, [%4];"
        : "=r"(r[0]), "=r"(r[1]), "=r"(r[2]), "=r"(r[3]) : "r"(addr));
}
#define CP_ASYNC16(s, g) \
    asm volatile("cp.async.ca.shared.global [%0], [%1], 16;" :: "r"(s), "l"(g))
#define CP_COMMIT()  asm volatile("cp.async.commit_group;" ::: "memory")
#define CP_WAIT1()   asm volatile("cp.async.wait_group 1;" ::: "memory")

// ===========================================================================
// k_prep_s12: blocks 0..255 -> fp16 permuted copy of W_in[512:768,:];
//             blocks 256..383 -> s12 GEMM (nodes @ W_in[0:512]) -> g_s12
__global__ void k_prep_s12(const float* __restrict__ nodes, const float* __restrict__ Win,
                           const float* __restrict__ b_in) {
    if (blockIdx.x < 256) {
        int k = blockIdx.x, n = threadIdx.x;
        int c = k >> 5, kg = (k >> 4) & 1, kk = k & 15;
        int t = (kk & 7) >> 1;
        int u = (kk & 1) + ((kk >> 3) << 1);
        int p = t * 4 + u;
        g_w3h[(((size_t)(c * 2 + kg)) * 256 + n) * 16 + p] =
            __float2half_rn(Win[(size_t)(512 + k) * 256 + n]);
        return;
    }
    __shared__ float As[16][64];
    __shared__ float Bs[16][64];
    int bx = blockIdx.x - 256;            // 0..127
    int tid = threadIdx.x;
    int tx = tid & 15, ty = tid >> 4;
    int row0 = (bx & 15) * 64;
    int n0   = (bx >> 4) * 64;
    float c[4][4] = {};
    for (int k0 = 0; k0 < 256; k0 += 16) {
        {
            int r = tid >> 2, kq = tid & 3;
            float4 v = *(const float4*)&nodes[(size_t)(row0 + r) * 256 + k0 + kq * 4];
            As[kq*4+0][r] = v.x; As[kq*4+1][r] = v.y; As[kq*4+2][r] = v.z; As[kq*4+3][r] = v.w;
        }
        {
            int k = tid >> 4, nq = tid & 15;
            int n = n0 + nq * 4;
            const float* src = (n < 256) ? &Win[(size_t)(k0 + k) * 256 + n]
                                         : &Win[(size_t)(256 + k0 + k) * 256 + (n - 256)];
            *(float4*)&Bs[k][nq*4] = *(const float4*)src;
        }
        __syncthreads();
#pragma unroll
        for (int k = 0; k < 16; k++) {
            float a[4], b[4];
            *(float4*)a = *(float4*)&As[k][ty*4];
            *(float4*)b = *(float4*)&Bs[k][tx*4];
#pragma unroll
            for (int i = 0; i < 4; i++)
#pragma unroll
                for (int j = 0; j < 4; j++) c[i][j] += a[i] * b[j];
        }
        __syncthreads();
    }
#pragma unroll
    for (int i = 0; i < 4; i++) {
        int row = row0 + ty*4 + i;
#pragma unroll
        for (int j = 0; j < 4; j++) {
            int n = n0 + tx*4 + j;
            float v = c[i][j] + (n >= 256 ? b_in[n - 256] : 0.f);
            g_s12[(size_t)row * 512 + n] = v;
        }
    }
}

// ===========================================================================
// k_main: fp16 mma m16n8k16, BM=64 x BN=256 x BK=32, 256 thr.
// Epilogue: tile (smem) -> coalesced cat store; softmax partials from tile.
#define A_STG_B 5120                     // 64 rows x 80B
#define B_STG_B 16384                    // 32k x 256n x 2B
#define TSTR    264                      // epilogue tile stride (floats)
#define OFF_A    0                       // 2 stages: 10240
#define OFF_B    10240                   // union: 3 B stages (49152) / tile (67584)
#define OFF_S1   77824
#define OFF_WC   78848
#define OFF_RED  79872                   // 64*4 floats
#define OFF_WROW 80896                   // 64 floats
#define SMEM_MAIN_BYTES 81152

__global__ void __launch_bounds__(256, 2) k_main(const float* __restrict__ edges,
                                                 const float* __restrict__ Wcoef,
                                                 const float* __restrict__ aux,
                                                 const float* __restrict__ bcoef,
                                                 float* __restrict__ cat) {
    extern __shared__ __align__(128) char smc[];
    float* s1s  = (float*)(smc + OFF_S1);
    float* wcs  = (float*)(smc + OFF_WC);
    float* red  = (float*)(smc + OFF_RED);
    float* wrow = (float*)(smc + OFF_WROW);
    float* tile = (float*)(smc + OFF_B);   // valid after mainloop (B stages dead)

    int tid = threadIdx.x;
    int lane = tid & 31, wid = tid >> 5;
    int gid = lane >> 2, tig = lane & 3;
    int wm = wid & 1, wn = wid >> 1;
    int m0w = wm * 32, n0w = wn * 64;

    int row0 = blockIdx.x * 64;
    int bi = row0 >> 8;
    int b  = bi >> 8;

    s1s[tid] = g_s12[(size_t)bi * 512 + tid];
    wcs[tid] = Wcoef[tid];

    int ar = tid >> 2, aj = tid & 3;
    const float* a_src = &edges[(size_t)(row0 + ar) * 256 + aj * 8];
    uint32_t a_sts = smem_u32(smc + OFF_A) + (uint32_t)(ar * 80 + aj * 16);

    uint32_t b_smem = smem_u32(smc + OFF_B);
    const char* b_gbase = (const char*)g_w3h;

    float4 rb[2][2];
    int lrow = ((lane >> 3) & 1) * 8 + (lane & 7);
    int lkb  = (lane >> 4) * 16;

#define LDGA(c, bf) do { \
        rb[bf][0] = *(const float4*)(a_src + (c) * 32); \
        rb[bf][1] = *(const float4*)(a_src + (c) * 32 + 4); } while (0)
#define STSA(c, bf) do { \
        uint4 t_; \
        t_.x = f2h2(rb[bf][0].x, rb[bf][0].y); \
        t_.y = f2h2(rb[bf][0].z, rb[bf][0].w); \
        t_.z = f2h2(rb[bf][1].x, rb[bf][1].y); \
        t_.w = f2h2(rb[bf][1].z, rb[bf][1].w); \
        asm volatile("st.shared.v4.b32 [%0], {%1,%2,%3,%4};" \
            :: "r"(a_sts + ((c) & 1) * A_STG_B), "r"(t_.x), "r"(t_.y), "r"(t_.z), "r"(t_.w) \
            : "memory"); } while (0)
#define CPB(c) do { \
        int s3_ = (c) - ((c) / 3) * 3; \
        _Pragma("unroll") \
        for (int i_ = 0; i_ < 4; i_++) { \
            int u_ = tid + i_ * 256; \
            int kg_ = u_ >> 9, n_ = (u_ >> 1) & 255, h_ = u_ & 1; \
            uint32_t d_ = b_smem + s3_ * B_STG_B + kg_ * 8192 + n_ * 32 + h_ * 16; \
            const void* s_ = b_gbase + (((size_t)((c) * 2 + kg_)) * 256 + n_) * 32 + h_ * 16; \
            CP_ASYNC16(d_, s_); \
        } } while (0)

    // ---- prologue
    LDGA(0, 0); LDGA(1, 1);
    CPB(0); CP_COMMIT();
    CPB(1); CP_COMMIT();
    STSA(0, 0);
    CP_WAIT1();
    __syncthreads();

    float acc[2][8][4] = {};

#pragma unroll
    for (int c = 0; c < 8; c++) {
        if (c + 2 < 8) CPB(c + 2);
        CP_COMMIT();
        if (c + 1 < 8) STSA(c + 1, (c + 1) & 1);
        if (c + 2 < 8) LDGA(c + 2, c & 1);

        uint32_t aBase = smem_u32(smc + OFF_A) + (c & 1) * A_STG_B;
        const char* Bs_ = smc + OFF_B + (c - (c / 3) * 3) * B_STG_B;
#pragma unroll
        for (int ks = 0; ks < 2; ks++) {
            uint32_t a[2][4];
#pragma unroll
            for (int mf = 0; mf < 2; mf++)
                ldsm4(a[mf], aBase + (uint32_t)((m0w + mf * 16 + lrow) * 80 + ks * 32 + lkb));
            uint32_t bf[8][2];
#pragma unroll
            for (int nf = 0; nf < 8; nf++) {
                int n = n0w + nf * 8 + gid;
                uint2 pv = *(const uint2*)(Bs_ + ks * 8192 + n * 32 + tig * 8);
                bf[nf][0] = pv.x; bf[nf][1] = pv.y;
            }
#pragma unroll
            for (int mf = 0; mf < 2; mf++)
#pragma unroll
                for (int nf = 0; nf < 8; nf++)
                    mma_f16(acc[mf][nf], a[mf], bf[nf]);
        }
        CP_WAIT1();
        __syncthreads();
    }

    // ---- epilogue 1: add s1/s2, relu, store TILE only, coef partials
#pragma unroll
    for (int mf = 0; mf < 2; mf++) {
#pragma unroll
        for (int rr = 0; rr < 2; rr++) {
            int row_local = m0w + mf * 16 + gid + rr * 8;
            int jj = (row0 & 255) + row_local;
            const float* s2p = &g_s12[((size_t)(b * 256 + jj)) * 512 + 256];
            float* tilep = &tile[(size_t)row_local * TSTR];
            float csum = 0.f;
#pragma unroll
            for (int nf = 0; nf < 8; nf++) {
                int nl = n0w + nf * 8 + tig * 2;
                float v0 = acc[mf][nf][rr*2]   + s1s[nl]   + s2p[nl];
                float v1 = acc[mf][nf][rr*2+1] + s1s[nl+1] + s2p[nl+1];
                v0 = fmaxf(v0, 0.f); v1 = fmaxf(v1, 0.f);
                csum += v0 * wcs[nl] + v1 * wcs[nl + 1];
                float2 st = { v0, v1 };
                *(float2*)&tilep[nl] = st;
            }
            csum += __shfl_xor_sync(0xffffffffu, csum, 1);
            csum += __shfl_xor_sync(0xffffffffu, csum, 2);
            if (tig == 0) red[row_local * 4 + wn] = csum;
        }
    }
    __syncthreads();

    // ---- epilogue 1.5: coalesced cat store from tile (16 x float4/thread)
    {
        float* catbase = &cat[(size_t)row0 * 256];
#pragma unroll
        for (int i = 0; i < 16; i++) {
            int idx = i * 1024 + tid * 4;
            int row = idx >> 8, col = idx & 255;
            float4 v = *(const float4*)&tile[(size_t)row * TSTR + col];
            *(float4*)&catbase[(size_t)row * 256 + col] = v;
        }
    }

    // ---- epilogue 2: w_j = exp(aux + coef + bc)
    if (tid < 64) {
        float coef = red[tid*4] + red[tid*4+1] + red[tid*4+2] + red[tid*4+3];
        wrow[tid] = __expf(aux[(size_t)row0 + tid] + coef + bcoef[0]);
    }
    __syncthreads();
    if (tid == 0) {
        float z = 0.f;
#pragma unroll
        for (int j = 0; j < 64; j++) z += wrow[j];
        g_zpart[blockIdx.x] = z;
    }

    // ---- epilogue 3: weighted column sums from the smem tile
    {
        float S = 0.f;
#pragma unroll 8
        for (int j = 0; j < 64; j++) S += wrow[j] * tile[(size_t)j * TSTR + tid];
        g_part[(size_t)blockIdx.x * 256 + tid] = S;
    }
}

// ===========================================================================
// k_out (fused reduce): resid rows computed in smem from g_part/g_zpart, then
// nodes + relu(resid @ W_out + b_out). BM=32 BN=64, grid (32,4).
__global__ void k_out(const float* __restrict__ nodes, const float* __restrict__ Wout,
                      const float* __restrict__ b_out, float* __restrict__ outn) {
    __shared__ float rs[32 * 256];        // resid rows [row][d]
    __shared__ float rz[32];
    __shared__ float Bs[16][64];
    int tid = threadIdx.x;
    int tx = tid & 15, ty = tid >> 4;
    int row0 = blockIdx.x * 32;
    int n0   = blockIdx.y * 64;

    if (tid < 32) {
        int q0 = (row0 + tid) * 4;
        float z = g_zpart[q0] + g_zpart[q0+1] + g_zpart[q0+2] + g_zpart[q0+3];
        rz[tid] = 1.f / z;
    }
    __syncthreads();
#pragma unroll 4
    for (int r = 0; r < 32; r++) {
        size_t q0 = (size_t)(row0 + r) * 4 * 256 + tid;
        float s = g_part[q0] + g_part[q0 + 256] + g_part[q0 + 512] + g_part[q0 + 768];
        rs[r * 256 + tid] = s * rz[r];
    }
    __syncthreads();

    float c[2][4] = {};
    for (int k0 = 0; k0 < 256; k0 += 16) {
        {
            int k = tid >> 4, nq = tid & 15;
            *(float4*)&Bs[k][nq*4] = *(const float4*)&Wout[(size_t)(k0 + k) * 256 + n0 + nq * 4];
        }
        __syncthreads();
#pragma unroll
        for (int k = 0; k < 16; k++) {
            float a0 = rs[(ty*2) * 256 + k0 + k];
            float a1 = rs[(ty*2+1) * 256 + k0 + k];
            float bb[4];
            *(float4*)bb = *(float4*)&Bs[k][tx*4];
#pragma unroll
            for (int j = 0; j < 4; j++) { c[0][j] += a0 * bb[j]; c[1][j] += a1 * bb[j]; }
        }
        __syncthreads();
    }
#pragma unroll
    for (int i = 0; i < 2; i++) {
        int row = row0 + ty*2 + i;
#pragma unroll
        for (int j = 0; j < 4; j++) {
            int n = n0 + tx*4 + j;
            float v = fmaxf(c[i][j] + b_out[n], 0.f);
            outn[(size_t)row * 256 + n] = nodes[(size_t)row * 256 + n] + v;
        }
    }
}

// ===========================================================================
extern "C" void kernel_launch(void* const* d_in, const int* in_sizes, int n_in,
                              void* d_out, int out_size) {
    const float* nodes = (const float*)d_in[0];
    const float* edges = (const float*)d_in[1];
    const float* aux   = (const float*)d_in[2];
    // d_in[3] = nums (unused)
    const float* Win   = (const float*)d_in[4];
    const float* b_in  = (const float*)d_in[5];
    const float* Wcoef = (const float*)d_in[6];
    const float* bcoef = (const float*)d_in[7];
    const float* Wout  = (const float*)d_in[8];
    const float* b_out = (const float*)d_in[9];

    float* out_nodes = (float*)d_out;                    // [4,256,256]
    float* out_cat   = out_nodes + (size_t)BIv * Dv;     // [4,256,256,256]

    cudaFuncSetAttribute(k_main, cudaFuncAttributeMaxDynamicSharedMemorySize,
                         SMEM_MAIN_BYTES);

    k_prep_s12<<<384, 256>>>(nodes, Win, b_in);
    k_main    <<<4096, 256, SMEM_MAIN_BYTES>>>(edges, Wcoef, aux, bcoef, out_cat);
    k_out     <<<dim3(32, 4), 256>>>(nodes, Wout, b_out, out_nodes);
}

// round 11
// speedup vs baseline: 1.5230x; 1.0221x over previous
#include <cuda_runtime.h>
#include <cuda_fp16.h>
#include <cstdint>
#include <cstring>

#define Bv 4
#define Nv 256
#define Dv 256
#define Mv (Bv*Nv*Nv)     // 262144 pair rows
#define BIv (Bv*Nv)       // 1024 (b,i) rows

// scratch (no allocations allowed)
__device__ __align__(16) float g_s12[BIv * 512];     // s1 (cols 0..255), s2+b_in (cols 256..511)
__device__ __align__(16) float g_part[4096 * 256];   // per-CTA weighted column partials
__device__ __align__(16) float g_zpart[4096];        // per-CTA exp-sum partials
// W_in[512:768,:] fp16, layout [c32][kg16][n][16perm]
__device__ __align__(16) __half g_w3h[256 * 256];

__device__ __forceinline__ uint32_t smem_u32(const void* p) {
    uint32_t a;
    asm("{ .reg .u64 t; cvta.to.shared.u64 t, %1; cvt.u32.u64 %0, t; }" : "=r"(a) : "l"(p));
    return a;
}
__device__ __forceinline__ uint32_t f2h2(float a, float b) {
    __half2 h = __floats2half2_rn(a, b);
    uint32_t u; memcpy(&u, &h, 4); return u;
}
__device__ __forceinline__ void mma_f16(float* d, const uint32_t* a, const uint32_t* b) {
    asm volatile(
        "mma.sync.aligned.m16n8k16.row.col.f32.f16.f16.f32 "
        "{%0,%1,%2,%3}, {%4,%5,%6,%7}, {%8,%9}, {%0,%1,%2,%3};"
        : "+f"(d[0]), "+f"(d[1]), "+f"(d[2]), "+f"(d[3])
        : "r"(a[0]), "r"(a[1]), "r"(a[2]), "r"(a[3]), "r"(b[0]), "r"(b[1]));
}
__device__ __forceinline__ void ldsm4(uint32_t* r, uint32_t addr) {
    asm volatile("ldmatrix.sync.aligned.m8n8.x4.shared.b16 {%0,%1,%2,%3}, [%4];"
        : "=r"(r[0]), "=r"(r[1]), "=r"(r[2]), "=r"(r[3]) : "r"(addr));
}
#define CP_ASYNC16(s, g) \
    asm volatile("cp.async.ca.shared.global [%0], [%1], 16;" :: "r"(s), "l"(g))
#define CP_COMMIT()  asm volatile("cp.async.commit_group;" ::: "memory")
#define CP_WAIT1()   asm volatile("cp.async.wait_group 1;" ::: "memory")

// ===========================================================================
// k_prep_s12: blocks 0..255 -> fp16 permuted copy of W_in[512:768,:];
//             blocks 256..383 -> s12 GEMM, cp.async double-buffered.
__global__ void k_prep_s12(const float* __restrict__ nodes, const float* __restrict__ Win,
                           const float* __restrict__ b_in) {
    if (blockIdx.x < 256) {
        int k = blockIdx.x, n = threadIdx.x;
        int c = k >> 5, kg = (k >> 4) & 1, kk = k & 15;
        int t = (kk & 7) >> 1;
        int u = (kk & 1) + ((kk >> 3) << 1);
        int p = t * 4 + u;
        g_w3h[(((size_t)(c * 2 + kg)) * 256 + n) * 16 + p] =
            __float2half_rn(Win[(size_t)(512 + k) * 256 + n]);
        return;
    }
    // ---- s12 GEMM: BM=64 x BN=64 x BK=16, 2-stage cp.async pipeline
    __shared__ float As[2][64 * 20];
    __shared__ float Bs[2][16 * 68];
    int bx = blockIdx.x - 256;            // 0..127
    int tid = threadIdx.x;
    int tx = tid & 15, ty = tid >> 4;
    int row0 = (bx & 15) * 64;
    int n0   = (bx >> 4) * 64;

    // cp.async mappings
    int arr = tid >> 2, aseg = tid & 3;   // A: 64 rows x 4 16B segments
    uint32_t a_dst = smem_u32(&As[0][0]) + (uint32_t)(arr * 20 + aseg * 4) * 4;
    const float* a_src = &nodes[(size_t)(row0 + arr) * 256 + aseg * 4];
    int bk = tid >> 4, bnq = tid & 15;    // B: 16 k x 16 16B segments
    int nn = n0 + bnq * 4;
    uint32_t b_dst = smem_u32(&Bs[0][0]) + (uint32_t)(bk * 68 + bnq * 4) * 4;
    const float* b_src = (nn < 256) ? &Win[(size_t)bk * 256 + nn]
                                    : &Win[(size_t)(256 + bk) * 256 + (nn - 256)];
    const uint32_t A_STG = 64 * 20 * 4;
    const uint32_t B_STG = 16 * 68 * 4;

    // prologue: chunks 0,1
    CP_ASYNC16(a_dst, (const void*)a_src);
    CP_ASYNC16(b_dst, (const void*)b_src);
    CP_COMMIT();
    CP_ASYNC16(a_dst + A_STG, (const void*)(a_src + 16));
    CP_ASYNC16(b_dst + B_STG, (const void*)(b_src + 16 * 256));
    CP_COMMIT();

    float c[4][4] = {};
    for (int ch = 0; ch < 16; ch++) {
        int s = ch & 1;
        CP_WAIT1();
        __syncthreads();
        const float* as = As[s];
        const float* bs = Bs[s];
#pragma unroll
        for (int k = 0; k < 16; k++) {
            float a[4], bb[4];
#pragma unroll
            for (int i = 0; i < 4; i++) a[i] = as[(ty * 4 + i) * 20 + k];
            *(float4*)bb = *(const float4*)&bs[k * 68 + tx * 4];
#pragma unroll
            for (int i = 0; i < 4; i++)
#pragma unroll
                for (int j = 0; j < 4; j++) c[i][j] += a[i] * bb[j];
        }
        __syncthreads();
        if (ch + 2 < 16) {
            int k0 = (ch + 2) * 16;
            CP_ASYNC16(a_dst + s * A_STG, (const void*)(a_src + k0));
            CP_ASYNC16(b_dst + s * B_STG, (const void*)(b_src + (size_t)k0 * 256));
        }
        CP_COMMIT();
    }
#pragma unroll
    for (int i = 0; i < 4; i++) {
        int row = row0 + ty * 4 + i;
#pragma unroll
        for (int j = 0; j < 4; j++) {
            int n = n0 + tx * 4 + j;
            float v = c[i][j] + (n >= 256 ? b_in[n - 256] : 0.f);
            g_s12[(size_t)row * 512 + n] = v;
        }
    }
}

// ===========================================================================
// k_main: fp16 mma m16n8k16, BM=64 x BN=256 x BK=32, 256 thr.
// Epilogue: tile (smem) -> coalesced cat store; softmax partials from tile.
#define A_STG_B 5120                     // 64 rows x 80B
#define B_STG_B 16384                    // 32k x 256n x 2B
#define TSTR    264                      // epilogue tile stride (floats)
#define OFF_A    0                       // 2 stages: 10240
#define OFF_B    10240                   // union: 3 B stages (49152) / tile (67584)
#define OFF_S1   77824
#define OFF_WC   78848
#define OFF_RED  79872                   // 64*4 floats
#define OFF_WROW 80896                   // 64 floats
#define SMEM_MAIN_BYTES 81152

__global__ void __launch_bounds__(256, 2) k_main(const float* __restrict__ edges,
                                                 const float* __restrict__ Wcoef,
                                                 const float* __restrict__ aux,
                                                 const float* __restrict__ bcoef,
                                                 float* __restrict__ cat) {
    extern __shared__ __align__(128) char smc[];
    float* s1s  = (float*)(smc + OFF_S1);
    float* wcs  = (float*)(smc + OFF_WC);
    float* red  = (float*)(smc + OFF_RED);
    float* wrow = (float*)(smc + OFF_WROW);
    float* tile = (float*)(smc + OFF_B);   // valid after mainloop (B stages dead)

    int tid = threadIdx.x;
    int lane = tid & 31, wid = tid >> 5;
    int gid = lane >> 2, tig = lane & 3;
    int wm = wid & 1, wn = wid >> 1;
    int m0w = wm * 32, n0w = wn * 64;

    int row0 = blockIdx.x * 64;
    int bi = row0 >> 8;
    int b  = bi >> 8;

    s1s[tid] = g_s12[(size_t)bi * 512 + tid];
    wcs[tid] = Wcoef[tid];

    int ar = tid >> 2, aj = tid & 3;
    const float* a_src = &edges[(size_t)(row0 + ar) * 256 + aj * 8];
    uint32_t a_sts = smem_u32(smc + OFF_A) + (uint32_t)(ar * 80 + aj * 16);

    uint32_t b_smem = smem_u32(smc + OFF_B);
    const char* b_gbase = (const char*)g_w3h;

    float4 rb[2][2];
    int lrow = ((lane >> 3) & 1) * 8 + (lane & 7);
    int lkb  = (lane >> 4) * 16;

#define LDGA(c, bf) do { \
        rb[bf][0] = *(const float4*)(a_src + (c) * 32); \
        rb[bf][1] = *(const float4*)(a_src + (c) * 32 + 4); } while (0)
#define STSA(c, bf) do { \
        uint4 t_; \
        t_.x = f2h2(rb[bf][0].x, rb[bf][0].y); \
        t_.y = f2h2(rb[bf][0].z, rb[bf][0].w); \
        t_.z = f2h2(rb[bf][1].x, rb[bf][1].y); \
        t_.w = f2h2(rb[bf][1].z, rb[bf][1].w); \
        asm volatile("st.shared.v4.b32 [%0], {%1,%2,%3,%4};" \
            :: "r"(a_sts + ((c) & 1) * A_STG_B), "r"(t_.x), "r"(t_.y), "r"(t_.z), "r"(t_.w) \
            : "memory"); } while (0)
#define CPB(c) do { \
        int s3_ = (c) - ((c) / 3) * 3; \
        _Pragma("unroll") \
        for (int i_ = 0; i_ < 4; i_++) { \
            int u_ = tid + i_ * 256; \
            int kg_ = u_ >> 9, n_ = (u_ >> 1) & 255, h_ = u_ & 1; \
            uint32_t d_ = b_smem + s3_ * B_STG_B + kg_ * 8192 + n_ * 32 + h_ * 16; \
            const void* s_ = b_gbase + (((size_t)((c) * 2 + kg_)) * 256 + n_) * 32 + h_ * 16; \
            CP_ASYNC16(d_, s_); \
        } } while (0)

    // ---- prologue
    LDGA(0, 0); LDGA(1, 1);
    CPB(0); CP_COMMIT();
    CPB(1); CP_COMMIT();
    STSA(0, 0);
    CP_WAIT1();
    __syncthreads();

    float acc[2][8][4] = {};

#pragma unroll
    for (int c = 0; c < 8; c++) {
        if (c + 2 < 8) CPB(c + 2);
        CP_COMMIT();
        if (c + 1 < 8) STSA(c + 1, (c + 1) & 1);
        if (c + 2 < 8) LDGA(c + 2, c & 1);

        uint32_t aBase = smem_u32(smc + OFF_A) + (c & 1) * A_STG_B;
        const char* Bs_ = smc + OFF_B + (c - (c / 3) * 3) * B_STG_B;
#pragma unroll
        for (int ks = 0; ks < 2; ks++) {
            uint32_t a[2][4];
#pragma unroll
            for (int mf = 0; mf < 2; mf++)
                ldsm4(a[mf], aBase + (uint32_t)((m0w + mf * 16 + lrow) * 80 + ks * 32 + lkb));
            uint32_t bf[8][2];
#pragma unroll
            for (int nf = 0; nf < 8; nf++) {
                int n = n0w + nf * 8 + gid;
                uint2 pv = *(const uint2*)(Bs_ + ks * 8192 + n * 32 + tig * 8);
                bf[nf][0] = pv.x; bf[nf][1] = pv.y;
            }
#pragma unroll
            for (int mf = 0; mf < 2; mf++)
#pragma unroll
                for (int nf = 0; nf < 8; nf++)
                    mma_f16(acc[mf][nf], a[mf], bf[nf]);
        }
        CP_WAIT1();
        __syncthreads();
    }

    // ---- epilogue 1: add s1/s2, relu, store TILE only, coef partials
#pragma unroll
    for (int mf = 0; mf < 2; mf++) {
#pragma unroll
        for (int rr = 0; rr < 2; rr++) {
            int row_local = m0w + mf * 16 + gid + rr * 8;
            int jj = (row0 & 255) + row_local;
            const float* s2p = &g_s12[((size_t)(b * 256 + jj)) * 512 + 256];
            float* tilep = &tile[(size_t)row_local * TSTR];
            float csum = 0.f;
#pragma unroll
            for (int nf = 0; nf < 8; nf++) {
                int nl = n0w + nf * 8 + tig * 2;
                float v0 = acc[mf][nf][rr*2]   + s1s[nl]   + s2p[nl];
                float v1 = acc[mf][nf][rr*2+1] + s1s[nl+1] + s2p[nl+1];
                v0 = fmaxf(v0, 0.f); v1 = fmaxf(v1, 0.f);
                csum += v0 * wcs[nl] + v1 * wcs[nl + 1];
                float2 st = { v0, v1 };
                *(float2*)&tilep[nl] = st;
            }
            csum += __shfl_xor_sync(0xffffffffu, csum, 1);
            csum += __shfl_xor_sync(0xffffffffu, csum, 2);
            if (tig == 0) red[row_local * 4 + wn] = csum;
        }
    }
    __syncthreads();

    // ---- epilogue 1.5: coalesced cat store from tile (16 x float4/thread)
    {
        float* catbase = &cat[(size_t)row0 * 256];
#pragma unroll
        for (int i = 0; i < 16; i++) {
            int idx = i * 1024 + tid * 4;
            int row = idx >> 8, col = idx & 255;
            float4 v = *(const float4*)&tile[(size_t)row * TSTR + col];
            *(float4*)&catbase[(size_t)row * 256 + col] = v;
        }
    }

    // ---- epilogue 2: w_j = exp(aux + coef + bc)
    if (tid < 64) {
        float coef = red[tid*4] + red[tid*4+1] + red[tid*4+2] + red[tid*4+3];
        wrow[tid] = __expf(aux[(size_t)row0 + tid] + coef + bcoef[0]);
    }
    __syncthreads();
    if (tid == 0) {
        float z = 0.f;
#pragma unroll
        for (int j = 0; j < 64; j++) z += wrow[j];
        g_zpart[blockIdx.x] = z;
    }

    // ---- epilogue 3: weighted column sums from the smem tile
    {
        float S = 0.f;
#pragma unroll 8
        for (int j = 0; j < 64; j++) S += wrow[j] * tile[(size_t)j * TSTR + tid];
        g_part[(size_t)blockIdx.x * 256 + tid] = S;
    }
}

// ===========================================================================
// k_out (fused reduce): resid rows computed in smem from g_part/g_zpart, then
// nodes + relu(resid @ W_out + b_out). BM=32 BN=64, grid (32,4).
__global__ void k_out(const float* __restrict__ nodes, const float* __restrict__ Wout,
                      const float* __restrict__ b_out, float* __restrict__ outn) {
    __shared__ float rs[32 * 256];        // resid rows [row][d]
    __shared__ float rz[32];
    __shared__ float Bs[16][64];
    int tid = threadIdx.x;
    int tx = tid & 15, ty = tid >> 4;
    int row0 = blockIdx.x * 32;
    int n0   = blockIdx.y * 64;

    if (tid < 32) {
        int q0 = (row0 + tid) * 4;
        float z = g_zpart[q0] + g_zpart[q0+1] + g_zpart[q0+2] + g_zpart[q0+3];
        rz[tid] = 1.f / z;
    }
    __syncthreads();
#pragma unroll 4
    for (int r = 0; r < 32; r++) {
        size_t q0 = (size_t)(row0 + r) * 4 * 256 + tid;
        float s = g_part[q0] + g_part[q0 + 256] + g_part[q0 + 512] + g_part[q0 + 768];
        rs[r * 256 + tid] = s * rz[r];
    }
    __syncthreads();

    float c[2][4] = {};
    for (int k0 = 0; k0 < 256; k0 += 16) {
        {
            int k = tid >> 4, nq = tid & 15;
            *(float4*)&Bs[k][nq*4] = *(const float4*)&Wout[(size_t)(k0 + k) * 256 + n0 + nq * 4];
        }
        __syncthreads();
#pragma unroll
        for (int k = 0; k < 16; k++) {
            float a0 = rs[(ty*2) * 256 + k0 + k];
            float a1 = rs[(ty*2+1) * 256 + k0 + k];
            float bb[4];
            *(float4*)bb = *(float4*)&Bs[k][tx*4];
#pragma unroll
            for (int j = 0; j < 4; j++) { c[0][j] += a0 * bb[j]; c[1][j] += a1 * bb[j]; }
        }
        __syncthreads();
    }
#pragma unroll
    for (int i = 0; i < 2; i++) {
        int row = row0 + ty*2 + i;
#pragma unroll
        for (int j = 0; j < 4; j++) {
            int n = n0 + tx*4 + j;
            float v = fmaxf(c[i][j] + b_out[n], 0.f);
            outn[(size_t)row * 256 + n] = nodes[(size_t)row * 256 + n] + v;
        }
    }
}

// ===========================================================================
extern "C" void kernel_launch(void* const* d_in, const int* in_sizes, int n_in,
                              void* d_out, int out_size) {
    const float* nodes = (const float*)d_in[0];
    const float* edges = (const float*)d_in[1];
    const float* aux   = (const float*)d_in[2];
    // d_in[3] = nums (unused)
    const float* Win   = (const float*)d_in[4];
    const float* b_in  = (const float*)d_in[5];
    const float* Wcoef = (const float*)d_in[6];
    const float* bcoef = (const float*)d_in[7];
    const float* Wout  = (const float*)d_in[8];
    const float* b_out = (const float*)d_in[9];

    float* out_nodes = (float*)d_out;                    // [4,256,256]
    float* out_cat   = out_nodes + (size_t)BIv * Dv;     // [4,256,256,256]

    cudaFuncSetAttribute(k_main, cudaFuncAttributeMaxDynamicSharedMemorySize,
                         SMEM_MAIN_BYTES);

    k_prep_s12<<<384, 256>>>(nodes, Win, b_in);
    k_main    <<<4096, 256, SMEM_MAIN_BYTES>>>(edges, Wcoef, aux, bcoef, out_cat);
    k_out     <<<dim3(32, 4), 256>>>(nodes, Wout, b_out, out_nodes);
}